// round 6
// baseline (speedup 1.0000x reference)
#include <cuda_runtime.h>

typedef unsigned long long ull;

#define THREADS 256
#define SEQ 512
#define DIN 120
#define NJ 25
#define NC 5
#define ROUTINGS 4
#define WROW 28         // padded W row (floats) -> 7 x 16B, LDS.128-aligned
#define CK 24           // k-chunk width
#define NCH 5           // 120 / 24
#define XSTR 25         // xs row stride (floats): gcd(25,32)=1 -> conflict-free

// dynamic shared layout (floats)
#define SM_W    0
#define SM_X    (SM_W + DIN*WROW)        // 3360
#define SM_RED  (SM_X + SEQ*XSTR)        // 16160
#define SM_SFIN (SM_RED + 8*26)          // 16368
#define SM_TOTF (SM_SFIN + 32)           // 16400 floats = 65600 B

__device__ __forceinline__ ull ffma2(ull a, ull b, ull c) {
    ull d;
    asm("fma.rn.f32x2 %0, %1, %2, %3;" : "=l"(d) : "l"(a), "l"(b), "l"(c));
    return d;
}
__device__ __forceinline__ ull pack2(float lo, float hi) {
    ull r; asm("mov.b64 %0, {%1, %2};" : "=l"(r) : "f"(lo), "f"(hi)); return r;
}
__device__ __forceinline__ void unpack2(ull v, float& lo, float& hi) {
    asm("mov.b64 {%0, %1}, %2;" : "=f"(lo), "=f"(hi) : "l"(v));
}

__global__ __launch_bounds__(THREADS, 3)
void caps_kernel(const float* __restrict__ x, const float* __restrict__ W,
                 float* __restrict__ out)
{
    extern __shared__ float sm[];
    float* Ws   = sm + SM_W;
    float* xs   = sm + SM_X;
    float* red  = sm + SM_RED;
    float* sfin = sm + SM_SFIN;

    const int tid = threadIdx.x;
    const int bb  = blockIdx.x;
    const float* xb = x + (size_t)bb * (SEQ * DIN);

    // ---- stage W into padded smem rows (k-major, 28 floats/row, zero pad) ----
    for (int idx = tid; idx < DIN * WROW; idx += THREADS) {
        int k = idx / WROW;
        int j = idx - k * WROW;
        Ws[idx] = (j < NJ) ? W[k * NJ + j] : 0.0f;
    }

    // ============== GEMM: thread owns full rows j0=tid, j1=tid+256 ==============
    const int j0 = tid, j1 = tid + THREADS;
    const float* xr0 = xs + j0 * XSTR;
    const float* xr1 = xs + j1 * XSTR;

    ull acc0[13], acc1[13];
    #pragma unroll
    for (int t = 0; t < 13; ++t) { acc0[t] = 0ull; acc1[t] = 0ull; }

    for (int c = 0; c < NCH; ++c) {
        __syncthreads();   // xs reuse guard (covers W load at c==0)

        // stage chunk: 512 rows x 24 cols, coalesced-ish float4 loads
        const int k0 = c * CK;
        #pragma unroll
        for (int m = 0; m < 12; ++m) {
            int idx = tid + THREADS * m;       // 0..3071 (512 rows x 6 float4)
            int row = idx / 6;
            int q   = idx - row * 6;
            const float4 v = *(const float4*)(xb + row * DIN + k0 + q * 4);
            float* p = xs + row * XSTR + q * 4;
            p[0] = v.x; p[1] = v.y; p[2] = v.z; p[3] = v.w;
        }
        __syncthreads();

        #pragma unroll 4
        for (int kk = 0; kk < CK; ++kk) {
            float av = xr0[kk];                 // conflict-free scalar LDS
            float bv = xr1[kk];
            ull a2 = pack2(av, av);
            ull b2 = pack2(bv, bv);
            const double2* wr = (const double2*)(Ws + (k0 + kk) * WROW);
            #pragma unroll
            for (int t = 0; t < 7; ++t) {
                double2 w = wr[t];              // uniform-address LDS.128 (broadcast)
                ull wlo = __double_as_longlong(w.x);
                acc0[2 * t] = ffma2(a2, wlo, acc0[2 * t]);
                acc1[2 * t] = ffma2(b2, wlo, acc1[2 * t]);
                if (t < 6) {
                    ull whi = __double_as_longlong(w.y);
                    acc0[2 * t + 1] = ffma2(a2, whi, acc0[2 * t + 1]);
                    acc1[2 * t + 1] = ffma2(b2, whi, acc1[2 * t + 1]);
                }
            }
        }
    }

    // accumulators become routing-resident u_hat rows
    float ua[26], ub[26];
    #pragma unroll
    for (int t = 0; t < 13; ++t) {
        unpack2(acc0[t], ua[2 * t], ua[2 * t + 1]);
        unpack2(acc1[t], ub[2 * t], ub[2 * t + 1]);
    }

    // ================= dynamic routing (4 iterations) =================
    float l0[NC] = {0, 0, 0, 0, 0};
    float l1[NC] = {0, 0, 0, 0, 0};
    const int wid  = tid >> 5;
    const int lane = tid & 31;

    for (int it = 0; it < ROUTINGS; ++it) {
        // softmax over the capsule axis (5)
        float c0[NC], c1[NC];
        {
            float m0 = l0[0], m1 = l1[0];
            #pragma unroll
            for (int i = 1; i < NC; ++i) { m0 = fmaxf(m0, l0[i]); m1 = fmaxf(m1, l1[i]); }
            float s0 = 0.f, s1 = 0.f;
            #pragma unroll
            for (int i = 0; i < NC; ++i) {
                c0[i] = __expf(l0[i] - m0); s0 += c0[i];
                c1[i] = __expf(l1[i] - m1); s1 += c1[i];
            }
            float r0 = __fdividef(1.f, s0), r1 = __fdividef(1.f, s1);
            #pragma unroll
            for (int i = 0; i < NC; ++i) { c0[i] *= r0; c1[i] *= r1; }
        }

        // partial s[i][k] over this thread's two rows
        float part[NJ];
        #pragma unroll
        for (int i = 0; i < NC; ++i)
            #pragma unroll
            for (int k = 0; k < NC; ++k)
                part[i * NC + k] = c0[i] * ua[i * NC + k] + c1[i] * ub[i * NC + k];

        // block reduce 25 values over 256 threads
        #pragma unroll
        for (int v = 0; v < NJ; ++v) {
            part[v] += __shfl_xor_sync(0xffffffffu, part[v], 16);
            part[v] += __shfl_xor_sync(0xffffffffu, part[v], 8);
            part[v] += __shfl_xor_sync(0xffffffffu, part[v], 4);
            part[v] += __shfl_xor_sync(0xffffffffu, part[v], 2);
            part[v] += __shfl_xor_sync(0xffffffffu, part[v], 1);
        }
        if (lane == 0) {
            #pragma unroll
            for (int v = 0; v < NJ; ++v) red[wid * 26 + v] = part[v];
        }
        __syncthreads();
        if (tid < NJ) {
            float a = 0.f;
            #pragma unroll
            for (int w = 0; w < 8; ++w) a += red[w * 26 + tid];
            sfin[tid] = a;
        }
        __syncthreads();

        // squash scale per capsule (broadcast read from smem)
        float inv[NC];
        #pragma unroll
        for (int i = 0; i < NC; ++i) {
            float n2 = 1e-7f;
            #pragma unroll
            for (int k = 0; k < NC; ++k) {
                float sv = sfin[i * NC + k];
                n2 += sv * sv;
            }
            inv[i] = rsqrtf(n2);
        }

        if (it < ROUTINGS - 1) {
            // b[i][j] = sum_k outputs[i][k] * u[i][j][k]   (replace, per reference)
            #pragma unroll
            for (int i = 0; i < NC; ++i) {
                float d0 = 0.f, d1 = 0.f;
                #pragma unroll
                for (int k = 0; k < NC; ++k) {
                    float o = sfin[i * NC + k] * inv[i];
                    d0 += o * ua[i * NC + k];
                    d1 += o * ub[i * NC + k];
                }
                l0[i] = d0; l1[i] = d1;
            }
        } else {
            if (tid < NJ) out[bb * NJ + tid] = sfin[tid] * inv[tid / NC];
        }
    }
}

extern "C" void kernel_launch(void* const* d_in, const int* in_sizes, int n_in,
                              void* d_out, int out_size) {
    const float* x = (const float*)d_in[0];
    const float* W = (const float*)d_in[1];
    float* out = (float*)d_out;
    int batch = in_sizes[0] / (SEQ * DIN);

    cudaFuncSetAttribute(caps_kernel, cudaFuncAttributeMaxDynamicSharedMemorySize,
                         SM_TOTF * (int)sizeof(float));
    caps_kernel<<<batch, THREADS, SM_TOTF * (int)sizeof(float)>>>(x, W, out);
}

// round 7
// speedup vs baseline: 1.0138x; 1.0138x over previous
#include <cuda_runtime.h>

typedef unsigned long long ull;

#define THREADS 256
#define SEQ 512
#define DIN 120
#define NJ 25
#define NC 5
#define ROUTINGS 4
#define WROW 28         // padded W row (floats) -> 7 x 16B, LDS.128-aligned
#define CK 24           // k-chunk width
#define NCH 5           // 120 / 24
#define XSTR 25         // slab row stride (floats): gcd(25,32)=1 -> conflict-free
#define SLAB (64 * XSTR)  // per-warp slab: 1600 floats

// dynamic shared layout (floats)
#define SM_W    0
#define SM_X    (SM_W + DIN*WROW)        // 3360
#define SM_RED  (SM_X + 8*SLAB)          // 16160
#define SM_SFIN (SM_RED + 8*26)          // 16368
#define SM_TOTF (SM_SFIN + 32)           // 16400 floats = 65600 B

__device__ __forceinline__ ull ffma2(ull a, ull b, ull c) {
    ull d;
    asm("fma.rn.f32x2 %0, %1, %2, %3;" : "=l"(d) : "l"(a), "l"(b), "l"(c));
    return d;
}
__device__ __forceinline__ ull pack2(float lo, float hi) {
    ull r; asm("mov.b64 %0, {%1, %2};" : "=l"(r) : "f"(lo), "f"(hi)); return r;
}
__device__ __forceinline__ void unpack2(ull v, float& lo, float& hi) {
    asm("mov.b64 {%0, %1}, %2;" : "=f"(lo), "=f"(hi) : "l"(v));
}

__global__ __launch_bounds__(THREADS, 3)
void caps_kernel(const float* __restrict__ x, const float* __restrict__ W,
                 float* __restrict__ out)
{
    extern __shared__ float sm[];
    float* Ws   = sm + SM_W;
    float* red  = sm + SM_RED;
    float* sfin = sm + SM_SFIN;

    const int tid  = threadIdx.x;
    const int wid  = tid >> 5;
    const int lane = tid & 31;
    const int bb   = blockIdx.x;
    const float* xb = x + (size_t)bb * (SEQ * DIN);

    // ---- stage W into padded smem rows (k-major, 28 floats/row, zero pad) ----
    for (int idx = tid; idx < DIN * WROW; idx += THREADS) {
        int k = idx / WROW;
        int j = idx - k * WROW;
        Ws[idx] = (j < NJ) ? W[k * NJ + j] : 0.0f;
    }
    __syncthreads();   // only block barrier before routing: W visible to all warps

    // ========== GEMM: warp owns 64 contiguous rows; thread owns 2 of them ==========
    // global rows: j0 = wid*64 + lane, j1 = wid*64 + 32 + lane
    float* slab = sm + SM_X + wid * SLAB;            // warp-private 64 x 25
    const float* xr0 = slab + lane * XSTR;
    const float* xr1 = slab + (lane + 32) * XSTR;
    const float* xw  = xb + (wid * 64) * DIN;        // warp's 64-row window

    ull acc0[13], acc1[13];
    #pragma unroll
    for (int t = 0; t < 13; ++t) { acc0[t] = 0ull; acc1[t] = 0ull; }

    for (int c = 0; c < NCH; ++c) {
        const int k0 = c * CK;
        __syncwarp();   // slab reuse guard (warp-local)

        // stage warp's 64 rows x 24 cols: 384 float4, 12 lane-strided iters
        #pragma unroll
        for (int m = 0; m < 12; ++m) {
            int idx = lane + 32 * m;        // 0..383
            int row = idx / 6;
            int q   = idx - row * 6;
            const float4 v = *(const float4*)(xw + row * DIN + k0 + q * 4);
            float* p = slab + row * XSTR + q * 4;
            p[0] = v.x; p[1] = v.y; p[2] = v.z; p[3] = v.w;
        }
        __syncwarp();

        #pragma unroll 4
        for (int kk = 0; kk < CK; ++kk) {
            float av = xr0[kk];                 // conflict-free scalar LDS
            float bv = xr1[kk];
            ull a2 = pack2(av, av);
            ull b2 = pack2(bv, bv);
            const double2* wr = (const double2*)(Ws + (k0 + kk) * WROW);
            #pragma unroll
            for (int t = 0; t < 7; ++t) {
                double2 w = wr[t];              // uniform-address LDS.128 (broadcast)
                ull wlo = __double_as_longlong(w.x);
                acc0[2 * t] = ffma2(a2, wlo, acc0[2 * t]);
                acc1[2 * t] = ffma2(b2, wlo, acc1[2 * t]);
                if (t < 6) {
                    ull whi = __double_as_longlong(w.y);
                    acc0[2 * t + 1] = ffma2(a2, whi, acc0[2 * t + 1]);
                    acc1[2 * t + 1] = ffma2(b2, whi, acc1[2 * t + 1]);
                }
            }
        }
    }

    // accumulators become routing-resident u_hat rows
    float ua[26], ub[26];
    #pragma unroll
    for (int t = 0; t < 13; ++t) {
        unpack2(acc0[t], ua[2 * t], ua[2 * t + 1]);
        unpack2(acc1[t], ub[2 * t], ub[2 * t + 1]);
    }

    // ================= dynamic routing (4 iterations) =================
    float l0[NC] = {0, 0, 0, 0, 0};
    float l1[NC] = {0, 0, 0, 0, 0};

    for (int it = 0; it < ROUTINGS; ++it) {
        // softmax over the capsule axis (5)
        float c0[NC], c1[NC];
        {
            float m0 = l0[0], m1 = l1[0];
            #pragma unroll
            for (int i = 1; i < NC; ++i) { m0 = fmaxf(m0, l0[i]); m1 = fmaxf(m1, l1[i]); }
            float s0 = 0.f, s1 = 0.f;
            #pragma unroll
            for (int i = 0; i < NC; ++i) {
                c0[i] = __expf(l0[i] - m0); s0 += c0[i];
                c1[i] = __expf(l1[i] - m1); s1 += c1[i];
            }
            float r0 = __fdividef(1.f, s0), r1 = __fdividef(1.f, s1);
            #pragma unroll
            for (int i = 0; i < NC; ++i) { c0[i] *= r0; c1[i] *= r1; }
        }

        // partial s[i][k] over this thread's two rows
        float part[NJ];
        #pragma unroll
        for (int i = 0; i < NC; ++i)
            #pragma unroll
            for (int k = 0; k < NC; ++k)
                part[i * NC + k] = c0[i] * ua[i * NC + k] + c1[i] * ub[i * NC + k];

        // block reduce 25 values over 256 threads
        #pragma unroll
        for (int v = 0; v < NJ; ++v) {
            part[v] += __shfl_xor_sync(0xffffffffu, part[v], 16);
            part[v] += __shfl_xor_sync(0xffffffffu, part[v], 8);
            part[v] += __shfl_xor_sync(0xffffffffu, part[v], 4);
            part[v] += __shfl_xor_sync(0xffffffffu, part[v], 2);
            part[v] += __shfl_xor_sync(0xffffffffu, part[v], 1);
        }
        if (lane == 0) {
            #pragma unroll
            for (int v = 0; v < NJ; ++v) red[wid * 26 + v] = part[v];
        }
        __syncthreads();
        if (tid < NJ) {
            float a = 0.f;
            #pragma unroll
            for (int w = 0; w < 8; ++w) a += red[w * 26 + tid];
            sfin[tid] = a;
        }
        __syncthreads();

        // squash scale per capsule (broadcast read from smem)
        float inv[NC];
        #pragma unroll
        for (int i = 0; i < NC; ++i) {
            float n2 = 1e-7f;
            #pragma unroll
            for (int k = 0; k < NC; ++k) {
                float sv = sfin[i * NC + k];
                n2 += sv * sv;
            }
            inv[i] = rsqrtf(n2);
        }

        if (it < ROUTINGS - 1) {
            // b[i][j] = sum_k outputs[i][k] * u[i][j][k]   (replace, per reference)
            #pragma unroll
            for (int i = 0; i < NC; ++i) {
                float d0 = 0.f, d1 = 0.f;
                #pragma unroll
                for (int k = 0; k < NC; ++k) {
                    float o = sfin[i * NC + k] * inv[i];
                    d0 += o * ua[i * NC + k];
                    d1 += o * ub[i * NC + k];
                }
                l0[i] = d0; l1[i] = d1;
            }
        } else {
            if (tid < NJ) out[bb * NJ + tid] = sfin[tid] * inv[tid / NC];
        }
    }
}

extern "C" void kernel_launch(void* const* d_in, const int* in_sizes, int n_in,
                              void* d_out, int out_size) {
    const float* x = (const float*)d_in[0];
    const float* W = (const float*)d_in[1];
    float* out = (float*)d_out;
    int batch = in_sizes[0] / (SEQ * DIN);

    cudaFuncSetAttribute(caps_kernel, cudaFuncAttributeMaxDynamicSharedMemorySize,
                         SM_TOTF * (int)sizeof(float));
    caps_kernel<<<batch, THREADS, SM_TOTF * (int)sizeof(float)>>>(x, W, out);
}

// round 9
// speedup vs baseline: 1.7005x; 1.6773x over previous
#include <cuda_runtime.h>

typedef unsigned long long ull;

#define THREADS 256
#define SEQ 512
#define DIN 120
#define NJ 25
#define NC 5
#define ROUTINGS 4
#define WROW 28   // padded W row (floats) -> 112B, 16B-aligned for .128 const loads

// W lives in constant memory: read on the constant port, NOT the L1/shared port.
// Zero-initialized; pad columns 25..27 stay 0 (cudaMemcpy2D only writes width bytes).
__constant__ float Wc[DIN * WROW];

__device__ __forceinline__ ull ffma2(ull a, ull b, ull c) {
    ull d;
    asm("fma.rn.f32x2 %0, %1, %2, %3;" : "=l"(d) : "l"(a), "l"(b), "l"(c));
    return d;
}
__device__ __forceinline__ ull pack2(float lo, float hi) {
    ull r; asm("mov.b64 %0, {%1, %2};" : "=l"(r) : "f"(lo), "f"(hi)); return r;
}
__device__ __forceinline__ void unpack2(ull v, float& lo, float& hi) {
    asm("mov.b64 {%0, %1}, %2;" : "=f"(lo), "=f"(hi) : "l"(v));
}

__global__ __launch_bounds__(THREADS, 3)
void caps_kernel(const float* __restrict__ x, float* __restrict__ out)
{
    __shared__ float red[8 * 26];    // per-warp routing partials
    __shared__ float sfin[32];       // reduced s[25]

    const int tid  = threadIdx.x;
    const int wid  = tid >> 5;
    const int lane = tid & 31;
    const int bb   = blockIdx.x;
    const float* xb = x + (size_t)bb * (SEQ * DIN);

    // ============ GEMM: thread computes full rows j0 = tid, j1 = tid + 256 ============
    // x: direct float4 LDG (L1-cached, each 128B line reused 8x across the k loop)
    // W: constant-port reads (double2 = LDC.128), zero L1 traffic
    const float4* pa = (const float4*)(xb + tid * DIN);             // 30 float4 / row
    const float4* pb = (const float4*)(xb + (tid + THREADS) * DIN);

    ull acc0[13], acc1[13];
    #pragma unroll
    for (int t = 0; t < 13; ++t) { acc0[t] = 0ull; acc1[t] = 0ull; }

    #pragma unroll 6
    for (int kc = 0; kc < 30; ++kc) {
        float4 va = pa[kc];
        float4 vb = pb[kc];
        #pragma unroll
        for (int q = 0; q < 4; ++q) {
            float av = (&va.x)[q];
            float bv = (&vb.x)[q];
            ull a2 = pack2(av, av);
            ull b2 = pack2(bv, bv);
            const double2* wr = (const double2*)(Wc + (kc * 4 + q) * WROW);
            #pragma unroll
            for (int t = 0; t < 7; ++t) {
                double2 w = wr[t];                       // constant-port .128 load
                ull wlo = __double_as_longlong(w.x);
                acc0[2 * t] = ffma2(a2, wlo, acc0[2 * t]);
                acc1[2 * t] = ffma2(b2, wlo, acc1[2 * t]);
                if (t < 6) {
                    ull whi = __double_as_longlong(w.y);
                    acc0[2 * t + 1] = ffma2(a2, whi, acc0[2 * t + 1]);
                    acc1[2 * t + 1] = ffma2(b2, whi, acc1[2 * t + 1]);
                }
            }
        }
    }

    // accumulators become routing-resident u_hat rows
    float ua[26], ub[26];
    #pragma unroll
    for (int t = 0; t < 13; ++t) {
        unpack2(acc0[t], ua[2 * t], ua[2 * t + 1]);
        unpack2(acc1[t], ub[2 * t], ub[2 * t + 1]);
    }

    // ================= dynamic routing (4 iterations) =================
    float l0[NC] = {0, 0, 0, 0, 0};
    float l1[NC] = {0, 0, 0, 0, 0};

    for (int it = 0; it < ROUTINGS; ++it) {
        // softmax over the capsule axis (5)
        float c0[NC], c1[NC];
        {
            float m0 = l0[0], m1 = l1[0];
            #pragma unroll
            for (int i = 1; i < NC; ++i) { m0 = fmaxf(m0, l0[i]); m1 = fmaxf(m1, l1[i]); }
            float s0 = 0.f, s1 = 0.f;
            #pragma unroll
            for (int i = 0; i < NC; ++i) {
                c0[i] = __expf(l0[i] - m0); s0 += c0[i];
                c1[i] = __expf(l1[i] - m1); s1 += c1[i];
            }
            float r0 = __fdividef(1.f, s0), r1 = __fdividef(1.f, s1);
            #pragma unroll
            for (int i = 0; i < NC; ++i) { c0[i] *= r0; c1[i] *= r1; }
        }

        // partial s[i][k] over this thread's two rows
        float part[NJ];
        #pragma unroll
        for (int i = 0; i < NC; ++i)
            #pragma unroll
            for (int k = 0; k < NC; ++k)
                part[i * NC + k] = c0[i] * ua[i * NC + k] + c1[i] * ub[i * NC + k];

        // block reduce 25 values over 256 threads
        #pragma unroll
        for (int v = 0; v < NJ; ++v) {
            part[v] += __shfl_xor_sync(0xffffffffu, part[v], 16);
            part[v] += __shfl_xor_sync(0xffffffffu, part[v], 8);
            part[v] += __shfl_xor_sync(0xffffffffu, part[v], 4);
            part[v] += __shfl_xor_sync(0xffffffffu, part[v], 2);
            part[v] += __shfl_xor_sync(0xffffffffu, part[v], 1);
        }
        if (lane == 0) {
            #pragma unroll
            for (int v = 0; v < NJ; ++v) red[wid * 26 + v] = part[v];
        }
        __syncthreads();
        if (tid < NJ) {
            float a = 0.f;
            #pragma unroll
            for (int w = 0; w < 8; ++w) a += red[w * 26 + tid];
            sfin[tid] = a;
        }
        __syncthreads();

        // squash scale per capsule (broadcast read from smem)
        float inv[NC];
        #pragma unroll
        for (int i = 0; i < NC; ++i) {
            float n2 = 1e-7f;
            #pragma unroll
            for (int k = 0; k < NC; ++k) {
                float sv = sfin[i * NC + k];
                n2 += sv * sv;
            }
            inv[i] = rsqrtf(n2);
        }

        if (it < ROUTINGS - 1) {
            // b[i][j] = sum_k outputs[i][k] * u[i][j][k]   (replace, per reference)
            #pragma unroll
            for (int i = 0; i < NC; ++i) {
                float d0 = 0.f, d1 = 0.f;
                #pragma unroll
                for (int k = 0; k < NC; ++k) {
                    float o = sfin[i * NC + k] * inv[i];
                    d0 += o * ua[i * NC + k];
                    d1 += o * ub[i * NC + k];
                }
                l0[i] = d0; l1[i] = d1;
            }
        } else {
            if (tid < NJ) out[bb * NJ + tid] = sfin[tid] * inv[tid / NC];
        }
    }
}

extern "C" void kernel_launch(void* const* d_in, const int* in_sizes, int n_in,
                              void* d_out, int out_size) {
    const float* x = (const float*)d_in[0];
    const float* W = (const float*)d_in[1];
    float* out = (float*)d_out;
    int batch = in_sizes[0] / (SEQ * DIN);

    // Fill constant W with 28-float padded rows (pad cols remain zero-initialized).
    // Device-to-device async 2D copy: graph-capturable, no allocation.
    void* wcAddr = nullptr;
    cudaGetSymbolAddress(&wcAddr, Wc);
    cudaMemcpy2DAsync(wcAddr, WROW * sizeof(float),
                      W, NJ * sizeof(float),
                      NJ * sizeof(float), DIN,
                      cudaMemcpyDeviceToDevice);

    caps_kernel<<<batch, THREADS>>>(x, out);
}